// round 13
// baseline (speedup 1.0000x reference)
#include <cuda_runtime.h>
#include <cuda_bf16.h>
#include <cstdint>
#include <math.h>
#include <float.h>

#define BATCH   131072
#define DIM     256
#define NCOL    208
#define NCOLP   224
#define NTILES  (BATCH / 128)    // 1024 tiles of 128 rows
#define NMB     (BATCH / 16)     // 8192 m16-blocks

// ---------------- device scratch (no runtime alloc) ----------------
// A planes, fragment-linear: [p][mblock][kstep][512B frag] ; 3*8192*16*512 = 201MB
__device__ uint4 g_afrag[(size_t)3 * NMB * 16 * 32];
// B planes, fragment-linear: [p][kstep][nblock 26][256B frag] = 319.5KB
__device__ uint2 g_wfrag[3 * 16 * 26 * 32];
__device__ float g_bpack[NCOLP];
__device__ float g_logits[(size_t)BATCH * NCOLP];   // ~117 MB

// ---------------- Threefry-2x32 (JAX partitionable mode) ----------------
__host__ __device__ __forceinline__ uint32_t rotl32(uint32_t x, int r) {
    return (x << r) | (x >> (32 - r));
}

__host__ __device__ __forceinline__ void threefry2x32(
    uint32_t k0, uint32_t k1, uint32_t x0, uint32_t x1,
    uint32_t& o0, uint32_t& o1)
{
    uint32_t ks2 = 0x1BD11BDAu ^ k0 ^ k1;
    x0 += k0; x1 += k1;
#define TF_RND(r) { x0 += x1; x1 = rotl32(x1, r); x1 ^= x0; }
    TF_RND(13) TF_RND(15) TF_RND(26) TF_RND(6)   x0 += k1;  x1 += ks2 + 1u;
    TF_RND(17) TF_RND(29) TF_RND(16) TF_RND(24)  x0 += ks2; x1 += k0  + 2u;
    TF_RND(13) TF_RND(15) TF_RND(26) TF_RND(6)   x0 += k0;  x1 += k1  + 3u;
    TF_RND(17) TF_RND(29) TF_RND(16) TF_RND(24)  x0 += k1;  x1 += ks2 + 4u;
    TF_RND(13) TF_RND(15) TF_RND(26) TF_RND(6)   x0 += ks2; x1 += k0  + 5u;
#undef TF_RND
    o0 = x0; o1 = x1;
}

__device__ __forceinline__ uint32_t tf_bits_part(uint32_t k0, uint32_t k1, uint32_t j) {
    uint32_t o0, o1;
    threefry2x32(k0, k1, 0u, j, o0, o1);
    return o0 ^ o1;
}

// Exact-path gumbel: bit-identical to JAX (precise logf).
__device__ __forceinline__ float bits_to_gumbel(uint32_t bits) {
    float f = __uint_as_float((bits >> 9) | 0x3f800000u) - 1.0f;
    float u = fmaxf(1.17549435e-38f, f + 1.17549435e-38f);
    return -logf(-logf(u));
}

struct SampKeys {
    uint32_t sc[8][2];
    uint32_t pw[2];
};

// ---------------- helpers ----------------
__device__ __forceinline__ void cp16(void* smem, const void* gmem) {
    uint32_t s = (uint32_t)__cvta_generic_to_shared(smem);
    asm volatile("cp.async.cg.shared.global [%0], [%1], 16;" :: "r"(s), "l"(gmem));
}
#define CP_COMMIT() asm volatile("cp.async.commit_group;")
#define CP_WAIT0()  asm volatile("cp.async.wait_group 0;")

// fp32 -> 3 exact bf16 residual planes
__device__ __forceinline__ void bsplit3(float v, unsigned short s[3]) {
    __nv_bfloat16 b0 = __float2bfloat16(v);
    float r1 = v - __bfloat162float(b0);
    __nv_bfloat16 b1 = __float2bfloat16(r1);
    float r2 = r1 - __bfloat162float(b1);
    __nv_bfloat16 b2 = __float2bfloat16(r2);
    s[0] = *(unsigned short*)&b0;
    s[1] = *(unsigned short*)&b1;
    s[2] = *(unsigned short*)&b2;
}

// split a float2 (lo,hi = consecutive k) into 3 packed bf16x2 words
__device__ __forceinline__ void split2(float2 v, uint32_t o[3]) {
    unsigned short a[3], b[3];
    bsplit3(v.x, a);
    bsplit3(v.y, b);
#pragma unroll
    for (int p = 0; p < 3; p++) o[p] = (uint32_t)a[p] | ((uint32_t)b[p] << 16);
}

#define MMA_BF16(ac, A, B0, B1) \
    asm volatile("mma.sync.aligned.m16n8k16.row.col.f32.bf16.bf16.f32 " \
        "{%0,%1,%2,%3}, {%4,%5,%6,%7}, {%8,%9}, {%0,%1,%2,%3};" \
        : "+f"((ac)[0]), "+f"((ac)[1]), "+f"((ac)[2]), "+f"((ac)[3]) \
        : "r"((A).x), "r"((A).y), "r"((A).z), "r"((A).w), "r"(B0), "r"(B1))

// ---------------- weight accessor (full fp32) ----------------
__device__ __forceinline__ float wAt(const float* Wsc, const float* Wpow, int d, int j) {
    if (j < 128) return Wsc[((j >> 4) * DIM + d) * 16 + (j & 15)];
    int jp = j - 128;
    return Wpow[((jp / 10) * DIM + d) * 10 + (jp % 10)];
}

// ---------------- pack B: weights -> bf16 plane fragments + bias ----------
__global__ void packB_kernel(const float* __restrict__ Wsc, const float* __restrict__ bsc,
                             const float* __restrict__ Wpow, const float* __restrict__ bpow)
{
    int idx = blockIdx.x * 256 + threadIdx.x;
    if (idx < NCOLP) {
        float bb = 0.0f;
        if (idx < 128)       bb = bsc[(idx >> 4) * 16 + (idx & 15)];
        else if (idx < NCOL) { int jp = idx - 128; bb = bpow[(jp / 10) * 10 + (jp % 10)]; }
        g_bpack[idx] = bb;
    }
    if (idx >= 26 * 16 * 32) return;
    int lane = idx & 31;
    int s    = (idx >> 5) & 15;
    int nb   = idx >> 9;                 // 0..25
    int n = nb * 8 + (lane >> 2);
    int k = s * 16 + (lane & 3) * 2;

    unsigned short sp[4][3];
    bsplit3(wAt(Wsc, Wpow, k,     n), sp[0]);
    bsplit3(wAt(Wsc, Wpow, k + 1, n), sp[1]);
    bsplit3(wAt(Wsc, Wpow, k + 8, n), sp[2]);
    bsplit3(wAt(Wsc, Wpow, k + 9, n), sp[3]);
#pragma unroll
    for (int p = 0; p < 3; p++) {
        uint32_t b0 = (uint32_t)sp[0][p] | ((uint32_t)sp[1][p] << 16);
        uint32_t b1 = (uint32_t)sp[2][p] | ((uint32_t)sp[3][p] << 16);
        g_wfrag[(size_t)((p * 16 + s) * 26 + nb) * 32 + lane] = make_uint2(b0, b1);
    }
}

// ---------------- convert x -> A plane fragments -----------------------
__global__ __launch_bounds__(256)
void convert_kernel(const float* __restrict__ x)
{
    int w = blockIdx.x * 8 + (threadIdx.x >> 5);   // warp id: 0..131071 = (mb, s)
    int lane = threadIdx.x & 31;
    int mb = w >> 4, s = w & 15;
    int r = lane >> 2, kk = (lane & 3) * 2;
    const float* xp = x + (size_t)(mb * 16) * DIM + s * 16;

    float2 v00 = *(const float2*)(xp + (size_t)r       * DIM + kk);       // a0
    float2 v10 = *(const float2*)(xp + (size_t)(r + 8) * DIM + kk);       // a1
    float2 v01 = *(const float2*)(xp + (size_t)r       * DIM + kk + 8);   // a2
    float2 v11 = *(const float2*)(xp + (size_t)(r + 8) * DIM + kk + 8);   // a3

    uint32_t w0[3], w1[3], w2[3], w3[3];
    split2(v00, w0); split2(v10, w1); split2(v01, w2); split2(v11, w3);

    size_t frag = (size_t)mb * 16 + s;
#pragma unroll
    for (int p = 0; p < 3; p++)
        g_afrag[(size_t)p * (NMB * 16) * 32 + frag * 32 + lane] =
            make_uint4(w0[p], w1[p], w2[p], w3[p]);
}

// ---------------- GEMM via mma.sync: CTA = 128 rows x (128|80) cols -------
#define G_SMEM 196608

template<int NB>    // nblocks per CTA: 16 (cols 0-127) or 10 (cols 128-207)
__device__ __forceinline__ void mma_body(char* sm, int tile, int nbBase)
{
    constexpr int WNB = NB / 2;
    const int tid  = threadIdx.x;
    const int lane = tid & 31;
    const int warp = tid >> 5;
    const int wm = warp >> 1;        // 0..3
    const int wn = warp & 1;         // 0..1

    // ---- load B slice into smem (one-time, L2-hot source) ----
    const char* gB = (const char*)g_wfrag;
    for (int c = tid; c < 3 * 16 * NB * 16; c += 256) {
        int ps  = c / (NB * 16);
        int rem = c - ps * (NB * 16);
        cp16(sm + (size_t)ps * (NB * 256) + rem * 16,
             gB + ((size_t)ps * 26 + nbBase) * 256 + rem * 16);
    }
    CP_COMMIT(); CP_WAIT0();
    __syncthreads();

    const int PA[6] = {0, 0, 1, 1, 0, 2};
    const int PB[6] = {0, 1, 0, 1, 2, 0};

    float acc[2][WNB][4];
#pragma unroll
    for (int mf = 0; mf < 2; mf++)
#pragma unroll
        for (int nf = 0; nf < WNB; nf++)
#pragma unroll
            for (int i = 0; i < 4; i++) acc[mf][nf][i] = 0.0f;

    const int mbG0 = tile * 8 + wm * 2;

    uint4 ring[3][2];
    auto loadA = [&](uint4* dst, int q) {
        int p = PA[q >> 4], s = q & 15;
#pragma unroll
        for (int mf = 0; mf < 2; mf++)
            dst[mf] = g_afrag[(size_t)p * (NMB * 16) * 32 +
                              ((size_t)(mbG0 + mf) * 16 + s) * 32 + lane];
    };
    loadA(ring[0], 0); loadA(ring[1], 1); loadA(ring[2], 2);

#pragma unroll 3
    for (int q = 0; q < 96; q++) {
        const int st = q % 3;
        uint4 a0 = ring[st][0], a1 = ring[st][1];
        if (q + 3 < 96) loadA(ring[st], q + 3);

        const int pb = PB[q >> 4], s = q & 15;
        const char* bs = sm + ((size_t)(pb * 16 + s) * NB + wn * WNB) * 256 + lane * 8;
        uint2 b[WNB];
#pragma unroll
        for (int nf = 0; nf < WNB; nf++) b[nf] = *(const uint2*)(bs + nf * 256);

#pragma unroll
        for (int nf = 0; nf < WNB; nf++) {
            MMA_BF16(acc[0][nf], a0, b[nf].x, b[nf].y);
            MMA_BF16(acc[1][nf], a1, b[nf].x, b[nf].y);
        }
    }

    // ---- epilogue: +bias, write f32 logits ----
    const int rbase = tile * 128 + wm * 32 + (lane >> 2);
#pragma unroll
    for (int mf = 0; mf < 2; mf++) {
#pragma unroll
        for (int nf = 0; nf < WNB; nf++) {
            int col = (nbBase + wn * WNB + nf) * 8 + (lane & 3) * 2;
            float2 bb = *(const float2*)&g_bpack[col];
            int row = rbase + mf * 16;
            *(float2*)&g_logits[(size_t)row * NCOLP + col] =
                make_float2(acc[mf][nf][0] + bb.x, acc[mf][nf][1] + bb.y);
            *(float2*)&g_logits[(size_t)(row + 8) * NCOLP + col] =
                make_float2(acc[mf][nf][2] + bb.x, acc[mf][nf][3] + bb.y);
        }
    }
}

__global__ __launch_bounds__(256, 1)
void gemm_kernel()
{
    extern __shared__ char sm[];
    const int tile = blockIdx.x >> 1;
    if ((blockIdx.x & 1) == 0) mma_body<16>(sm, tile, 0);
    else                       mma_body<10>(sm, tile, 16);
}

// ---------------- sampler (unchanged from R6/R12) ----------------
__global__ __launch_bounds__(256)
void sample_kernel(const int* __restrict__ avail, float* __restrict__ out, SampKeys keys)
{
    __shared__ float Ls[256][18];

    const int t = threadIdx.x;
    const int row0 = blockIdx.x * 256;
    const int b = row0 + t;

    const float NEG = -10000000000.0f;
    unsigned cnt = 0;
    float lp = 0.0f;

    for (int u = 0; u < 8; u++) {
        __syncthreads();
#pragma unroll
        for (int i = 0; i < 4; i++) {
            int e4 = t + i * 256;
            int row = e4 >> 2, c4 = e4 & 3;
            float4 v = *(const float4*)&g_logits[(size_t)(row0 + row) * NCOLP + u * 16 + c4 * 4];
            *(float2*)&Ls[row][c4 * 4]     = make_float2(v.x, v.y);
            *(float2*)&Ls[row][c4 * 4 + 2] = make_float2(v.z, v.w);
        }
        __syncthreads();
        const float* L = Ls[t];

        const uint32_t k0 = keys.sc[u][0], k1 = keys.sc[u][1];
        int a = 0;
        float best = -INFINITY, m = -INFINITY;
        float ml[16];
#pragma unroll
        for (int c = 0; c < 16; c++) {
            ml[c] = (((cnt >> (2 * c)) & 3u) < 2u) ? L[c] : NEG;
            float g = bits_to_gumbel(tf_bits_part(k0, k1, (uint32_t)(b * 16 + c)));
            float z = g + ml[c];
            if (z > best) { best = z; a = c; }
            m = fmaxf(m, ml[c]);
        }
        float s = 0.0f;
#pragma unroll
        for (int c = 0; c < 16; c++) s += __expf(ml[c] - m);
        float lg = (ml[a] - m) - __logf(s);
        int av = avail[b * 16 + u];
        out[(size_t)b * 16 + u] = (av > 0) ? (float)a : -1.0f;
        if (av > 0) { lp += lg; cnt += 1u << (2 * a); }
    }

    for (int h = 0; h < 8; h++) {
        __syncthreads();
#pragma unroll
        for (int i = 0; i < 5; i++) {
            int e2 = t + i * 256;
            int row = e2 / 5, c2 = e2 - row * 5;
            float2 v = *(const float2*)&g_logits[(size_t)(row0 + row) * NCOLP + 128 + h * 10 + c2 * 2];
            *(float2*)&Ls[row][c2 * 2] = v;
        }
        __syncthreads();
        const float* L = Ls[t];

        int a = 0;
        float best = -INFINITY, m = -INFINITY;
#pragma unroll
        for (int k = 0; k < 10; k++) {
            float g = bits_to_gumbel(tf_bits_part(keys.pw[0], keys.pw[1],
                                                  (uint32_t)(b * 80 + h * 10 + k)));
            float z = g + L[k];
            if (z > best) { best = z; a = k; }
            m = fmaxf(m, L[k]);
        }
        float s = 0.0f;
#pragma unroll
        for (int k = 0; k < 10; k++) s += __expf(L[k] - m);
        float lg = (L[a] - m) - __logf(s);
        int av = avail[b * 16 + 8 + h];
        out[(size_t)b * 16 + 8 + h] = (av > 0) ? (float)a : -1.0f;
        if (av > 0) lp += lg;
    }

    out[(size_t)BATCH * 16 + b] = lp;

    const size_t OFF = (size_t)BATCH * 17;
#pragma unroll
    for (int i = 0; i < 4; i++) {
        int4 v = *(const int4*)&avail[b * 16 + i * 4];
        *(float4*)&out[OFF + (size_t)b * 16 + i * 4] =
            make_float4((float)v.x, (float)v.y, (float)v.z, (float)v.w);
    }
}

// ---------------- host ----------------
extern "C" void kernel_launch(void* const* d_in, const int* in_sizes, int n_in,
                              void* d_out, int out_size)
{
    const float* x     = (const float*)d_in[0];
    const int*   avail = (const int*)  d_in[1];
    const float* Wsc   = (const float*)d_in[2];
    const float* bsc   = (const float*)d_in[3];
    const float* Wpow  = (const float*)d_in[4];
    const float* bpow  = (const float*)d_in[5];
    float* out = (float*)d_out;

    // JAX key(42) -> [0,42]; partitionable fold-like split + fold_in.
    SampKeys keys;
    for (int u = 0; u < 8; u++) {
        uint32_t o0, o1;
        threefry2x32(0u, 42u, 0u, (uint32_t)u, o0, o1);
        keys.sc[u][0] = o0; keys.sc[u][1] = o1;
    }
    threefry2x32(0u, 42u, 0u, 999u, keys.pw[0], keys.pw[1]);

    cudaFuncSetAttribute(gemm_kernel, cudaFuncAttributeMaxDynamicSharedMemorySize, G_SMEM);

    packB_kernel<<<(26 * 16 * 32 + 255) / 256, 256>>>(Wsc, bsc, Wpow, bpow);
    convert_kernel<<<(NMB * 16) / 8, 256>>>(x);
    gemm_kernel<<<NTILES * 2, 256, G_SMEM>>>();
    sample_kernel<<<BATCH / 256, 256>>>(avail, out, keys);
}

// round 14
// speedup vs baseline: 1.0374x; 1.0374x over previous
#include <cuda_runtime.h>
#include <cuda_bf16.h>
#include <cstdint>
#include <math.h>
#include <float.h>

#define BATCH   131072
#define DIM     256
#define NCOL    208
#define NCOLP   224
#define NTILES  (BATCH / 128)    // 1024 tiles of 128 rows

// ---------------- device scratch (no runtime alloc) ----------------
// B planes, fragment-linear: [p][kstep][nblock 26][256B frag] = 319.5KB (L2-hot)
__device__ uint2 g_wfrag[3 * 16 * 26 * 32];
__device__ float g_bpack[NCOLP];
__device__ float g_logits[(size_t)BATCH * NCOLP];   // ~117 MB

// ---------------- Threefry-2x32 (JAX partitionable mode) ----------------
__host__ __device__ __forceinline__ uint32_t rotl32(uint32_t x, int r) {
    return (x << r) | (x >> (32 - r));
}

__host__ __device__ __forceinline__ void threefry2x32(
    uint32_t k0, uint32_t k1, uint32_t x0, uint32_t x1,
    uint32_t& o0, uint32_t& o1)
{
    uint32_t ks2 = 0x1BD11BDAu ^ k0 ^ k1;
    x0 += k0; x1 += k1;
#define TF_RND(r) { x0 += x1; x1 = rotl32(x1, r); x1 ^= x0; }
    TF_RND(13) TF_RND(15) TF_RND(26) TF_RND(6)   x0 += k1;  x1 += ks2 + 1u;
    TF_RND(17) TF_RND(29) TF_RND(16) TF_RND(24)  x0 += ks2; x1 += k0  + 2u;
    TF_RND(13) TF_RND(15) TF_RND(26) TF_RND(6)   x0 += k0;  x1 += k1  + 3u;
    TF_RND(17) TF_RND(29) TF_RND(16) TF_RND(24)  x0 += k1;  x1 += ks2 + 4u;
    TF_RND(13) TF_RND(15) TF_RND(26) TF_RND(6)   x0 += ks2; x1 += k0  + 5u;
#undef TF_RND
    o0 = x0; o1 = x1;
}

__device__ __forceinline__ uint32_t tf_bits_part(uint32_t k0, uint32_t k1, uint32_t j) {
    uint32_t o0, o1;
    threefry2x32(k0, k1, 0u, j, o0, o1);
    return o0 ^ o1;
}

// Exact-path gumbel: bit-identical to JAX (precise logf).
__device__ __forceinline__ float bits_to_gumbel(uint32_t bits) {
    float f = __uint_as_float((bits >> 9) | 0x3f800000u) - 1.0f;
    float u = fmaxf(1.17549435e-38f, f + 1.17549435e-38f);
    return -logf(-logf(u));
}

struct SampKeys {
    uint32_t sc[8][2];
    uint32_t pw[2];
};

// ---------------- helpers ----------------
__device__ __forceinline__ void cp16(void* smem, const void* gmem) {
    uint32_t s = (uint32_t)__cvta_generic_to_shared(smem);
    asm volatile("cp.async.cg.shared.global [%0], [%1], 16;" :: "r"(s), "l"(gmem));
}
#define CP_COMMIT() asm volatile("cp.async.commit_group;")
#define CP_WAIT0()  asm volatile("cp.async.wait_group 0;")

// fp32 -> 3 exact bf16 residual planes
__device__ __forceinline__ void bsplit3(float v, unsigned short s[3]) {
    __nv_bfloat16 b0 = __float2bfloat16(v);
    float r1 = v - __bfloat162float(b0);
    __nv_bfloat16 b1 = __float2bfloat16(r1);
    float r2 = r1 - __bfloat162float(b1);
    __nv_bfloat16 b2 = __float2bfloat16(r2);
    s[0] = *(unsigned short*)&b0;
    s[1] = *(unsigned short*)&b1;
    s[2] = *(unsigned short*)&b2;
}

// split a float2 (consecutive k) into 3 packed bf16x2 words
__device__ __forceinline__ void split2(float2 v, uint32_t o[3]) {
    unsigned short a[3], b[3];
    bsplit3(v.x, a);
    bsplit3(v.y, b);
#pragma unroll
    for (int p = 0; p < 3; p++) o[p] = (uint32_t)a[p] | ((uint32_t)b[p] << 16);
}

#define MMA_BF16(ac, a0, a1, a2, a3, B0, B1) \
    asm volatile("mma.sync.aligned.m16n8k16.row.col.f32.bf16.bf16.f32 " \
        "{%0,%1,%2,%3}, {%4,%5,%6,%7}, {%8,%9}, {%0,%1,%2,%3};" \
        : "+f"((ac)[0]), "+f"((ac)[1]), "+f"((ac)[2]), "+f"((ac)[3]) \
        : "r"(a0), "r"(a1), "r"(a2), "r"(a3), "r"(B0), "r"(B1))

// ---------------- weight accessor (full fp32) ----------------
__device__ __forceinline__ float wAt(const float* Wsc, const float* Wpow, int d, int j) {
    if (j < 128) return Wsc[((j >> 4) * DIM + d) * 16 + (j & 15)];
    int jp = j - 128;
    return Wpow[((jp / 10) * DIM + d) * 10 + (jp % 10)];
}

// ---------------- pack B: weights -> bf16 plane fragments + bias ----------
__global__ void packB_kernel(const float* __restrict__ Wsc, const float* __restrict__ bsc,
                             const float* __restrict__ Wpow, const float* __restrict__ bpow)
{
    int idx = blockIdx.x * 256 + threadIdx.x;
    if (idx < NCOLP) {
        float bb = 0.0f;
        if (idx < 128)       bb = bsc[(idx >> 4) * 16 + (idx & 15)];
        else if (idx < NCOL) { int jp = idx - 128; bb = bpow[(jp / 10) * 10 + (jp % 10)]; }
        g_bpack[idx] = bb;
    }
    if (idx >= 26 * 16 * 32) return;
    int lane = idx & 31;
    int s    = (idx >> 5) & 15;
    int nb   = idx >> 9;                 // 0..25
    int n = nb * 8 + (lane >> 2);
    int k = s * 16 + (lane & 3) * 2;

    unsigned short sp[4][3];
    bsplit3(wAt(Wsc, Wpow, k,     n), sp[0]);
    bsplit3(wAt(Wsc, Wpow, k + 1, n), sp[1]);
    bsplit3(wAt(Wsc, Wpow, k + 8, n), sp[2]);
    bsplit3(wAt(Wsc, Wpow, k + 9, n), sp[3]);
#pragma unroll
    for (int p = 0; p < 3; p++) {
        uint32_t b0 = (uint32_t)sp[0][p] | ((uint32_t)sp[1][p] << 16);
        uint32_t b1 = (uint32_t)sp[2][p] | ((uint32_t)sp[3][p] << 16);
        g_wfrag[(size_t)((p * 16 + s) * 26 + nb) * 32 + lane] = make_uint2(b0, b1);
    }
}

// ---------------- fused GEMM: convert-in-register + mma.sync ---------------
// CTA = 128 rows x (128|80) cols; K in 4 chunks of 64; x staged f32 in smem;
// A planes produced per-warp in registers; B chunk double-buffered in smem.
#define XROWB 272                    // padded x row stride bytes (68 floats)
#define XS_BYTES (128 * XROWB)       // 34816 per buffer
#define OFF_XS 0                     // 2 buffers: 69632
#define OFF_BS 69632                 // 2 x (3*4*NB*256)
#define G_SMEM (69632 + 2 * 3 * 4 * 16 * 256)   // 167936 (NB=16 worst case)

__device__ __constant__ int c_PA[6] = {0, 0, 1, 1, 0, 2};
__device__ __constant__ int c_PB[6] = {0, 1, 0, 1, 2, 0};

template<int NB>    // nblocks per CTA: 16 (cols 0-127) or 10 (cols 128-207)
__device__ __forceinline__ void mma_body(char* sm, const float* __restrict__ x,
                                         int tile, int nbBase)
{
    constexpr int WNB = NB / 2;
    constexpr int BCHUNK = 3 * 4 * NB * 256;     // B bytes per k-chunk

    const int tid  = threadIdx.x;
    const int lane = tid & 31;
    const int warp = tid >> 5;
    const int wm = warp >> 1;        // 0..3  (rows wm*32..wm*32+31)
    const int wn = warp & 1;         // 0..1

    char* XS = sm + OFF_XS;
    char* BS = sm + OFF_BS;

    const int row0 = tile * 128;

    auto issue_loads = [&](int chunk, int buf) {
        // x: 128 rows x 64 floats = 2048 f4, 8 per thread
        const float* xc = x + (size_t)row0 * DIM + chunk * 64;
        char* xd = XS + buf * XS_BYTES;
#pragma unroll
        for (int i = 0; i < 8; i++) {
            int f = tid + i * 256;
            int row = f >> 4, q = f & 15;
            cp16(xd + row * XROWB + q * 16, xc + (size_t)row * DIM + q * 4);
        }
        // B chunk: 3 planes x 4 s x NB nb x 256B
        const char* gB = (const char*)g_wfrag;
        char* bd = BS + buf * BCHUNK;
        for (int c = tid; c < 3 * 4 * NB * 16; c += 256) {
            int inner = c & 15;
            int t = c >> 4;                 // ((p*4+sl)*NB + nb)
            int nb = t % NB;
            int t2 = t / NB;                // p*4 + sl
            int sl = t2 & 3, p = t2 >> 2;
            cp16(bd + c * 16,
                 gB + ((size_t)(p * 16 + chunk * 4 + sl) * 26 + nbBase + nb) * 256 + inner * 16);
        }
        CP_COMMIT();
    };

    float acc[2][WNB][4];
#pragma unroll
    for (int mf = 0; mf < 2; mf++)
#pragma unroll
        for (int nf = 0; nf < WNB; nf++)
#pragma unroll
            for (int i = 0; i < 4; i++) acc[mf][nf][i] = 0.0f;

    issue_loads(0, 0);
    CP_WAIT0();
    __syncthreads();

    const int r  = lane >> 2;
    const int kk = (lane & 3) * 2;

    for (int chunk = 0; chunk < 4; chunk++) {
        const int cur = chunk & 1;
        if (chunk + 1 < 4) issue_loads(chunk + 1, cur ^ 1);

        const char* xb = XS + cur * XS_BYTES;
        const char* bb = BS + cur * BCHUNK;

#pragma unroll
        for (int sl = 0; sl < 4; sl++) {
            // ---- convert A fragment for both m-frags, 3 planes, in regs ----
            uint32_t Aw[2][3][4];
#pragma unroll
            for (int mf = 0; mf < 2; mf++) {
                const int mrow = (wm * 2 + mf) * 16;
                const char* base = xb + (size_t)(mrow + r) * XROWB + (sl * 16 + kk) * 4;
                float2 v0 = *(const float2*)base;                        // (r, k)
                float2 v1 = *(const float2*)(base + 8 * XROWB);          // (r+8, k)
                float2 v2 = *(const float2*)(base + 32);                 // (r, k+8)
                float2 v3 = *(const float2*)(base + 8 * XROWB + 32);     // (r+8, k+8)
                uint32_t w0[3], w1[3], w2[3], w3[3];
                split2(v0, w0); split2(v1, w1); split2(v2, w2); split2(v3, w3);
#pragma unroll
                for (int p = 0; p < 3; p++) {
                    Aw[mf][p][0] = w0[p]; Aw[mf][p][1] = w1[p];
                    Aw[mf][p][2] = w2[p]; Aw[mf][p][3] = w3[p];
                }
            }
            // ---- 6 products ----
#pragma unroll
            for (int prod = 0; prod < 6; prod++) {
                const int pa = c_PA[prod], pb = c_PB[prod];
                const char* bs = bb + ((size_t)(pb * 4 + sl) * NB + wn * WNB) * 256 + lane * 8;
                uint2 b[WNB];
#pragma unroll
                for (int nf = 0; nf < WNB; nf++) b[nf] = *(const uint2*)(bs + nf * 256);
#pragma unroll
                for (int nf = 0; nf < WNB; nf++) {
                    MMA_BF16(acc[0][nf], Aw[0][pa][0], Aw[0][pa][1], Aw[0][pa][2], Aw[0][pa][3],
                             b[nf].x, b[nf].y);
                    MMA_BF16(acc[1][nf], Aw[1][pa][0], Aw[1][pa][1], Aw[1][pa][2], Aw[1][pa][3],
                             b[nf].x, b[nf].y);
                }
            }
        }

        if (chunk + 1 < 4) CP_WAIT0();
        __syncthreads();
    }

    // ---- epilogue: +bias, write f32 logits ----
    const int rbase = tile * 128 + wm * 32 + (lane >> 2);
#pragma unroll
    for (int mf = 0; mf < 2; mf++) {
#pragma unroll
        for (int nf = 0; nf < WNB; nf++) {
            int col = (nbBase + wn * WNB + nf) * 8 + (lane & 3) * 2;
            float2 bv = *(const float2*)&g_bpack[col];
            int row = rbase + mf * 16;
            *(float2*)&g_logits[(size_t)row * NCOLP + col] =
                make_float2(acc[mf][nf][0] + bv.x, acc[mf][nf][1] + bv.y);
            *(float2*)&g_logits[(size_t)(row + 8) * NCOLP + col] =
                make_float2(acc[mf][nf][2] + bv.x, acc[mf][nf][3] + bv.y);
        }
    }
}

__global__ __launch_bounds__(256, 1)
void gemm_kernel(const float* __restrict__ x)
{
    extern __shared__ char sm[];
    const int tile = blockIdx.x >> 1;
    if ((blockIdx.x & 1) == 0) mma_body<16>(sm, x, tile, 0);
    else                       mma_body<10>(sm, x, tile, 16);
}

// ---------------- sampler (unchanged; at its issue floor) ----------------
__global__ __launch_bounds__(256)
void sample_kernel(const int* __restrict__ avail, float* __restrict__ out, SampKeys keys)
{
    __shared__ float Ls[256][18];

    const int t = threadIdx.x;
    const int row0 = blockIdx.x * 256;
    const int b = row0 + t;

    const float NEG = -10000000000.0f;
    unsigned cnt = 0;
    float lp = 0.0f;

    for (int u = 0; u < 8; u++) {
        __syncthreads();
#pragma unroll
        for (int i = 0; i < 4; i++) {
            int e4 = t + i * 256;
            int row = e4 >> 2, c4 = e4 & 3;
            float4 v = *(const float4*)&g_logits[(size_t)(row0 + row) * NCOLP + u * 16 + c4 * 4];
            *(float2*)&Ls[row][c4 * 4]     = make_float2(v.x, v.y);
            *(float2*)&Ls[row][c4 * 4 + 2] = make_float2(v.z, v.w);
        }
        __syncthreads();
        const float* L = Ls[t];

        const uint32_t k0 = keys.sc[u][0], k1 = keys.sc[u][1];
        int a = 0;
        float best = -INFINITY, m = -INFINITY;
        float ml[16];
#pragma unroll
        for (int c = 0; c < 16; c++) {
            ml[c] = (((cnt >> (2 * c)) & 3u) < 2u) ? L[c] : NEG;
            float g = bits_to_gumbel(tf_bits_part(k0, k1, (uint32_t)(b * 16 + c)));
            float z = g + ml[c];
            if (z > best) { best = z; a = c; }
            m = fmaxf(m, ml[c]);
        }
        float s = 0.0f;
#pragma unroll
        for (int c = 0; c < 16; c++) s += __expf(ml[c] - m);
        float lg = (ml[a] - m) - __logf(s);
        int av = avail[b * 16 + u];
        out[(size_t)b * 16 + u] = (av > 0) ? (float)a : -1.0f;
        if (av > 0) { lp += lg; cnt += 1u << (2 * a); }
    }

    for (int h = 0; h < 8; h++) {
        __syncthreads();
#pragma unroll
        for (int i = 0; i < 5; i++) {
            int e2 = t + i * 256;
            int row = e2 / 5, c2 = e2 - row * 5;
            float2 v = *(const float2*)&g_logits[(size_t)(row0 + row) * NCOLP + 128 + h * 10 + c2 * 2];
            *(float2*)&Ls[row][c2 * 2] = v;
        }
        __syncthreads();
        const float* L = Ls[t];

        int a = 0;
        float best = -INFINITY, m = -INFINITY;
#pragma unroll
        for (int k = 0; k < 10; k++) {
            float g = bits_to_gumbel(tf_bits_part(keys.pw[0], keys.pw[1],
                                                  (uint32_t)(b * 80 + h * 10 + k)));
            float z = g + L[k];
            if (z > best) { best = z; a = k; }
            m = fmaxf(m, L[k]);
        }
        float s = 0.0f;
#pragma unroll
        for (int k = 0; k < 10; k++) s += __expf(L[k] - m);
        float lg = (L[a] - m) - __logf(s);
        int av = avail[b * 16 + 8 + h];
        out[(size_t)b * 16 + 8 + h] = (av > 0) ? (float)a : -1.0f;
        if (av > 0) lp += lg;
    }

    out[(size_t)BATCH * 16 + b] = lp;

    const size_t OFF = (size_t)BATCH * 17;
#pragma unroll
    for (int i = 0; i < 4; i++) {
        int4 v = *(const int4*)&avail[b * 16 + i * 4];
        *(float4*)&out[OFF + (size_t)b * 16 + i * 4] =
            make_float4((float)v.x, (float)v.y, (float)v.z, (float)v.w);
    }
}

// ---------------- host ----------------
extern "C" void kernel_launch(void* const* d_in, const int* in_sizes, int n_in,
                              void* d_out, int out_size)
{
    const float* x     = (const float*)d_in[0];
    const int*   avail = (const int*)  d_in[1];
    const float* Wsc   = (const float*)d_in[2];
    const float* bsc   = (const float*)d_in[3];
    const float* Wpow  = (const float*)d_in[4];
    const float* bpow  = (const float*)d_in[5];
    float* out = (float*)d_out;

    // JAX key(42) -> [0,42]; partitionable fold-like split + fold_in.
    SampKeys keys;
    for (int u = 0; u < 8; u++) {
        uint32_t o0, o1;
        threefry2x32(0u, 42u, 0u, (uint32_t)u, o0, o1);
        keys.sc[u][0] = o0; keys.sc[u][1] = o1;
    }
    threefry2x32(0u, 42u, 0u, 999u, keys.pw[0], keys.pw[1]);

    cudaFuncSetAttribute(gemm_kernel, cudaFuncAttributeMaxDynamicSharedMemorySize, G_SMEM);

    packB_kernel<<<(26 * 16 * 32 + 255) / 256, 256>>>(Wsc, bsc, Wpow, bpow);
    gemm_kernel<<<NTILES * 2, 256, G_SMEM>>>(x);
    sample_kernel<<<BATCH / 256, 256>>>(avail, out, keys);
}

// round 17
// speedup vs baseline: 1.2353x; 1.1907x over previous
#include <cuda_runtime.h>
#include <cuda_bf16.h>
#include <cstdint>
#include <math.h>
#include <float.h>

#define BATCH   131072
#define DIM     256
#define NCOL    208
#define NCOLP   224
#define NTILES  (BATCH / 128)    // 1024 tiles of 128 rows

// ---------------- device scratch (no runtime alloc) ----------------
__device__ uint2 g_wfrag[3 * 16 * 26 * 32];          // bf16 B-plane frags (L2-hot)
__device__ float g_wpack[DIM * NCOLP];               // f32 weights [d][224]
__device__ float g_bpack[NCOLP];
__device__ float g_logits[(size_t)BATCH * NCOLP];    // ~117 MB

// ---------------- Threefry-2x32 (JAX partitionable mode) ----------------
__host__ __device__ __forceinline__ uint32_t rotl32(uint32_t x, int r) {
    return (x << r) | (x >> (32 - r));
}

__host__ __device__ __forceinline__ void threefry2x32(
    uint32_t k0, uint32_t k1, uint32_t x0, uint32_t x1,
    uint32_t& o0, uint32_t& o1)
{
    uint32_t ks2 = 0x1BD11BDAu ^ k0 ^ k1;
    x0 += k0; x1 += k1;
#define TF_RND(r) { x0 += x1; x1 = rotl32(x1, r); x1 ^= x0; }
    TF_RND(13) TF_RND(15) TF_RND(26) TF_RND(6)   x0 += k1;  x1 += ks2 + 1u;
    TF_RND(17) TF_RND(29) TF_RND(16) TF_RND(24)  x0 += ks2; x1 += k0  + 2u;
    TF_RND(13) TF_RND(15) TF_RND(26) TF_RND(6)   x0 += k0;  x1 += k1  + 3u;
    TF_RND(17) TF_RND(29) TF_RND(16) TF_RND(24)  x0 += k1;  x1 += ks2 + 4u;
    TF_RND(13) TF_RND(15) TF_RND(26) TF_RND(6)   x0 += ks2; x1 += k0  + 5u;
#undef TF_RND
    o0 = x0; o1 = x1;
}

__device__ __forceinline__ uint32_t tf_bits_part(uint32_t k0, uint32_t k1, uint32_t j) {
    uint32_t o0, o1;
    threefry2x32(k0, k1, 0u, j, o0, o1);
    return o0 ^ o1;
}

// Exact-path gumbel: bit-identical to JAX (precise logf).
__device__ __forceinline__ float bits_to_gumbel(uint32_t bits) {
    float f = __uint_as_float((bits >> 9) | 0x3f800000u) - 1.0f;
    float u = fmaxf(1.17549435e-38f, f + 1.17549435e-38f);
    return -logf(-logf(u));
}

struct SampKeys {
    uint32_t sc[8][2];
    uint32_t pw[2];
};

// ---------------- helpers ----------------
typedef unsigned long long ull;

__device__ __forceinline__ ull pack2(float x) {
    ull r; asm("mov.b64 %0, {%1, %1};" : "=l"(r) : "f"(x)); return r;
}
__device__ __forceinline__ void fma2(ull& d, ull a, ull b) {
    asm("fma.rn.f32x2 %0, %1, %2, %0;" : "+l"(d) : "l"(a), "l"(b));
}
__device__ __forceinline__ void unpack2(ull v, float& lo, float& hi) {
    asm("mov.b64 {%0, %1}, %2;" : "=f"(lo), "=f"(hi) : "l"(v));
}
__device__ __forceinline__ void cp16(void* smem, const void* gmem) {
    uint32_t s = (uint32_t)__cvta_generic_to_shared(smem);
    asm volatile("cp.async.cg.shared.global [%0], [%1], 16;" :: "r"(s), "l"(gmem));
}
#define CP_COMMIT() asm volatile("cp.async.commit_group;")
#define CP_WAIT0()  asm volatile("cp.async.wait_group 0;")

// Cross-role rendezvous (legal divergent pattern: arrivers at one PC,
// sync-ers at one PC, per barrier). Tensor role = A, SIMT role = B.
#define RDV_A() do { \
    asm volatile("bar.arrive 1, 256;" ::: "memory"); \
    asm volatile("bar.sync   2, 256;" ::: "memory"); \
} while (0)
#define RDV_B() do { \
    asm volatile("bar.sync   1, 256;" ::: "memory"); \
    asm volatile("bar.arrive 2, 256;" ::: "memory"); \
} while (0)

// fp32 -> 3 exact bf16 residual planes
__device__ __forceinline__ void bsplit3(float v, unsigned short s[3]) {
    __nv_bfloat16 b0 = __float2bfloat16(v);
    float r1 = v - __bfloat162float(b0);
    __nv_bfloat16 b1 = __float2bfloat16(r1);
    float r2 = r1 - __bfloat162float(b1);
    __nv_bfloat16 b2 = __float2bfloat16(r2);
    s[0] = *(unsigned short*)&b0;
    s[1] = *(unsigned short*)&b1;
    s[2] = *(unsigned short*)&b2;
}

__device__ __forceinline__ void split2(float2 v, uint32_t o[3]) {
    unsigned short a[3], b[3];
    bsplit3(v.x, a);
    bsplit3(v.y, b);
#pragma unroll
    for (int p = 0; p < 3; p++) o[p] = (uint32_t)a[p] | ((uint32_t)b[p] << 16);
}

#define MMA_BF16(ac, a0, a1, a2, a3, B0, B1) \
    asm volatile("mma.sync.aligned.m16n8k16.row.col.f32.bf16.bf16.f32 " \
        "{%0,%1,%2,%3}, {%4,%5,%6,%7}, {%8,%9}, {%0,%1,%2,%3};" \
        : "+f"((ac)[0]), "+f"((ac)[1]), "+f"((ac)[2]), "+f"((ac)[3]) \
        : "r"(a0), "r"(a1), "r"(a2), "r"(a3), "r"(B0), "r"(B1))

__device__ __forceinline__ float wAt(const float* Wsc, const float* Wpow, int d, int j) {
    if (j < 128) return Wsc[((j >> 4) * DIM + d) * 16 + (j & 15)];
    int jp = j - 128;
    return Wpow[((jp / 10) * DIM + d) * 10 + (jp % 10)];
}

// ---------------- pack kernels ----------------
__global__ void pack_kernel(const float* __restrict__ Wsc, const float* __restrict__ bsc,
                            const float* __restrict__ Wpow, const float* __restrict__ bpow)
{
    int idx = blockIdx.x * blockDim.x + threadIdx.x;
    if (idx >= DIM * NCOLP) return;
    int d = idx / NCOLP;
    int j = idx - d * NCOLP;
    float w = 0.0f;
    if (j < NCOL) w = wAt(Wsc, Wpow, d, j);
    g_wpack[d * NCOLP + j] = w;
    if (d == 0) {
        float bb = 0.0f;
        if (j < 128)       bb = bsc[(j >> 4) * 16 + (j & 15)];
        else if (j < NCOL) { int jp = j - 128; bb = bpow[(jp / 10) * 10 + (jp % 10)]; }
        g_bpack[j] = bb;
    }
}

__global__ void packB_kernel(const float* __restrict__ Wsc, const float* __restrict__ Wpow)
{
    int idx = blockIdx.x * 256 + threadIdx.x;
    if (idx >= 26 * 16 * 32) return;
    int lane = idx & 31;
    int s    = (idx >> 5) & 15;
    int nb   = idx >> 9;
    int n = nb * 8 + (lane >> 2);
    int k = s * 16 + (lane & 3) * 2;

    unsigned short sp[4][3];
    bsplit3(wAt(Wsc, Wpow, k,     n), sp[0]);
    bsplit3(wAt(Wsc, Wpow, k + 1, n), sp[1]);
    bsplit3(wAt(Wsc, Wpow, k + 8, n), sp[2]);
    bsplit3(wAt(Wsc, Wpow, k + 9, n), sp[3]);
#pragma unroll
    for (int p = 0; p < 3; p++) {
        uint32_t b0 = (uint32_t)sp[0][p] | ((uint32_t)sp[1][p] << 16);
        uint32_t b1 = (uint32_t)sp[2][p] | ((uint32_t)sp[3][p] << 16);
        g_wfrag[(size_t)((p * 16 + s) * 26 + nb) * 32 + lane] = make_uint2(b0, b1);
    }
}

// ---------------- dual-pipe GEMM: tensor cols 0-95, FFMA2 cols 96-207 ------
#define XROWB 272                        // 68 f32 per row (64 data + pad)
#define XS_B  (128 * XROWB)              // 34816 per buffer
#define OFF_XS 0                         // 2 bufs: 69632
#define OFF_BF 69632                     // 2 x 3*4*12*256 = 73728
#define BF_B  36864
#define OFF_WS 143360                    // 2 x 64*112*4 = 57344
#define WS_B  28672
#define G_SMEM 200704

__device__ __constant__ int c_PA[6] = {0, 0, 1, 1, 0, 2};
__device__ __constant__ int c_PB[6] = {0, 1, 0, 1, 2, 0};

__global__ __launch_bounds__(256, 1)
void gemm_kernel(const float* __restrict__ x)
{
    extern __shared__ char sm[];
    const int tid  = threadIdx.x;
    const int lane = tid & 31;
    const int warp = tid >> 5;
    const int row0 = blockIdx.x * 128;

    char* XS = sm + OFF_XS;
    char* BF = sm + OFF_BF;
    char* WS = sm + OFF_WS;

    if (warp < 4) {
        // ================= tensor role (A): cols 0..95 (12 nblocks) =========
        const int wm = warp;

        auto stage = [&](int chunk, int buf) {
            const float* xc = x + (size_t)row0 * DIM + chunk * 64;
            char* xd = XS + buf * XS_B;
#pragma unroll
            for (int i = 0; i < 8; i++) {
                int f = tid + i * 128;               // rows 0..63
                int row = f >> 4, q = f & 15;
                cp16(xd + row * XROWB + q * 16, xc + (size_t)row * DIM + q * 4);
            }
            const char* gB = (const char*)g_wfrag;
            char* bd = BF + buf * BF_B;
#pragma unroll
            for (int i = 0; i < 18; i++) {
                int c = tid + i * 128;               // 0..2303
                int inner = c & 15;
                int t = c >> 4;
                int nb = t % 12;
                int t2 = t / 12;                     // p*4 + sl
                int sl = t2 & 3, p = t2 >> 2;
                cp16(bd + (t2 * 12 + nb) * 256 + inner * 16,
                     gB + ((size_t)(p * 16 + chunk * 4 + sl) * 26 + nb) * 256 + inner * 16);
            }
            CP_COMMIT();
        };

        float acc[2][12][4];
#pragma unroll
        for (int mf = 0; mf < 2; mf++)
#pragma unroll
            for (int nf = 0; nf < 12; nf++)
#pragma unroll
                for (int i = 0; i < 4; i++) acc[mf][nf][i] = 0.0f;

        stage(0, 0);
        CP_WAIT0();
        RDV_A();

        const int r  = lane >> 2;
        const int kk = (lane & 3) * 2;

        for (int chunk = 0; chunk < 4; chunk++) {
            const int cur = chunk & 1;
            if (chunk < 3) stage(chunk + 1, cur ^ 1);

            const char* xb = XS + cur * XS_B;
            const char* bb = BF + cur * BF_B;

#pragma unroll
            for (int sl = 0; sl < 4; sl++) {
                uint32_t Aw[2][3][4];
#pragma unroll
                for (int mf = 0; mf < 2; mf++) {
                    const int mrow = (wm * 2 + mf) * 16;
                    const char* base = xb + (size_t)(mrow + r) * XROWB + (sl * 16 + kk) * 4;
                    float2 v0 = *(const float2*)base;
                    float2 v1 = *(const float2*)(base + 8 * XROWB);
                    float2 v2 = *(const float2*)(base + 32);
                    float2 v3 = *(const float2*)(base + 8 * XROWB + 32);
                    uint32_t w0[3], w1[3], w2[3], w3[3];
                    split2(v0, w0); split2(v1, w1); split2(v2, w2); split2(v3, w3);
#pragma unroll
                    for (int p = 0; p < 3; p++) {
                        Aw[mf][p][0] = w0[p]; Aw[mf][p][1] = w1[p];
                        Aw[mf][p][2] = w2[p]; Aw[mf][p][3] = w3[p];
                    }
                }
#pragma unroll
                for (int prod = 0; prod < 6; prod++) {
                    const int pa = c_PA[prod], pb = c_PB[prod];
                    const char* bs = bb + (size_t)((pb * 4 + sl) * 12) * 256 + lane * 8;
#pragma unroll
                    for (int nf = 0; nf < 12; nf++) {
                        uint2 b = *(const uint2*)(bs + nf * 256);
                        MMA_BF16(acc[0][nf], Aw[0][pa][0], Aw[0][pa][1], Aw[0][pa][2], Aw[0][pa][3], b.x, b.y);
                        MMA_BF16(acc[1][nf], Aw[1][pa][0], Aw[1][pa][1], Aw[1][pa][2], Aw[1][pa][3], b.x, b.y);
                    }
                }
            }

            if (chunk < 3) CP_WAIT0();
            RDV_A();
        }

        // epilogue: cols 0..95
        const int rbase = row0 + wm * 32 + (lane >> 2);
#pragma unroll
        for (int mf = 0; mf < 2; mf++) {
#pragma unroll
            for (int nf = 0; nf < 12; nf++) {
                int col = nf * 8 + (lane & 3) * 2;
                float2 bv = *(const float2*)&g_bpack[col];
                int row = rbase + mf * 16;
                *(float2*)&g_logits[(size_t)row * NCOLP + col] =
                    make_float2(acc[mf][nf][0] + bv.x, acc[mf][nf][1] + bv.y);
                *(float2*)&g_logits[(size_t)(row + 8) * NCOLP + col] =
                    make_float2(acc[mf][nf][2] + bv.x, acc[mf][nf][3] + bv.y);
            }
        }
    } else {
        // ================= SIMT role (B): cols 96..207 (112 cols) ===========
        const int st = tid - 128;
        const int ty = st >> 2;              // 0..31 -> 4 rows each
        const int tx = st & 3;               // 0..3  -> 28 cols each
        const int col0 = 96 + tx * 28;

        auto stage = [&](int chunk, int buf) {
            const float* xc = x + (size_t)row0 * DIM + chunk * 64;
            char* xd = XS + buf * XS_B;
#pragma unroll
            for (int i = 0; i < 8; i++) {
                int f = st + i * 128 + 1024;          // rows 64..127
                int row = f >> 4, q = f & 15;
                cp16(xd + row * XROWB + q * 16, xc + (size_t)row * DIM + q * 4);
            }
            char* wd = WS + buf * WS_B;
#pragma unroll
            for (int i = 0; i < 14; i++) {
                int f = st + i * 128;                 // 0..1791
                int k = f / 28, j = f - k * 28;
                cp16(wd + (k * 112 + j * 4) * 4,
                     g_wpack + (size_t)(chunk * 64 + k) * NCOLP + 96 + j * 4);
            }
            CP_COMMIT();
        };

        ull acc[4][14];
#pragma unroll
        for (int r = 0; r < 4; r++)
#pragma unroll
            for (int c = 0; c < 14; c++) acc[r][c] = 0ULL;

        stage(0, 0);
        CP_WAIT0();
        RDV_B();

        for (int chunk = 0; chunk < 4; chunk++) {
            const int cur = chunk & 1;
            if (chunk < 3) stage(chunk + 1, cur ^ 1);

            const char* xb = XS + cur * XS_B;
            const float* wb = (const float*)(WS + cur * WS_B);

#pragma unroll 4
            for (int q = 0; q < 16; q++) {
                float4 a4[4];
#pragma unroll
                for (int r = 0; r < 4; r++)
                    a4[r] = *(const float4*)(xb + (size_t)(ty * 4 + r) * XROWB + q * 16);
#pragma unroll
                for (int j = 0; j < 4; j++) {
                    ull b2[14];
#pragma unroll
                    for (int c = 0; c < 14; c++)
                        b2[c] = *(const ull*)&wb[(q * 4 + j) * 112 + tx * 28 + 2 * c];
#pragma unroll
                    for (int r = 0; r < 4; r++) {
                        float aj = ((const float*)&a4[r])[j];
                        ull a2 = pack2(aj);
#pragma unroll
                        for (int c = 0; c < 14; c++) fma2(acc[r][c], a2, b2[c]);
                    }
                }
            }

            if (chunk < 3) CP_WAIT0();
            RDV_B();
        }

        // epilogue: cols 96..207  (bias buffer now covers all 28 thread cols)
        float bb[28];
#pragma unroll
        for (int c = 0; c < 28; c++) bb[c] = g_bpack[col0 + c];
#pragma unroll
        for (int r = 0; r < 4; r++) {
            const size_t rowoff = (size_t)(row0 + ty * 4 + r) * NCOLP + col0;
#pragma unroll
            for (int c = 0; c < 7; c++) {
                float lo, hi;
                unpack2(acc[r][2 * c], lo, hi);
                float lo2, hi2;
                unpack2(acc[r][2 * c + 1], lo2, hi2);
                *(float4*)&g_logits[rowoff + 4 * c] =
                    make_float4(lo + bb[4 * c], hi + bb[4 * c + 1],
                                lo2 + bb[4 * c + 2], hi2 + bb[4 * c + 3]);
            }
        }
    }
}

// ---------------- sampler (R12, unchanged) ----------------
__global__ __launch_bounds__(256)
void sample_kernel(const int* __restrict__ avail, float* __restrict__ out, SampKeys keys)
{
    __shared__ float Ls[256][18];

    const int t = threadIdx.x;
    const int row0 = blockIdx.x * 256;
    const int b = row0 + t;

    const float NEG = -10000000000.0f;
    unsigned cnt = 0;
    float lp = 0.0f;

    for (int u = 0; u < 8; u++) {
        __syncthreads();
#pragma unroll
        for (int i = 0; i < 4; i++) {
            int e4 = t + i * 256;
            int row = e4 >> 2, c4 = e4 & 3;
            float4 v = *(const float4*)&g_logits[(size_t)(row0 + row) * NCOLP + u * 16 + c4 * 4];
            *(float2*)&Ls[row][c4 * 4]     = make_float2(v.x, v.y);
            *(float2*)&Ls[row][c4 * 4 + 2] = make_float2(v.z, v.w);
        }
        __syncthreads();
        const float* L = Ls[t];

        const uint32_t k0 = keys.sc[u][0], k1 = keys.sc[u][1];
        int a = 0;
        float best = -INFINITY, m = -INFINITY;
        float ml[16];
#pragma unroll
        for (int c = 0; c < 16; c++) {
            ml[c] = (((cnt >> (2 * c)) & 3u) < 2u) ? L[c] : NEG;
            float g = bits_to_gumbel(tf_bits_part(k0, k1, (uint32_t)(b * 16 + c)));
            float z = g + ml[c];
            if (z > best) { best = z; a = c; }
            m = fmaxf(m, ml[c]);
        }
        float s = 0.0f;
#pragma unroll
        for (int c = 0; c < 16; c++) s += __expf(ml[c] - m);
        float lg = (ml[a] - m) - __logf(s);
        int av = avail[b * 16 + u];
        out[(size_t)b * 16 + u] = (av > 0) ? (float)a : -1.0f;
        if (av > 0) { lp += lg; cnt += 1u << (2 * a); }
    }

    for (int h = 0; h < 8; h++) {
        __syncthreads();
#pragma unroll
        for (int i = 0; i < 5; i++) {
            int e2 = t + i * 256;
            int row = e2 / 5, c2 = e2 - row * 5;
            float2 v = *(const float2*)&g_logits[(size_t)(row0 + row) * NCOLP + 128 + h * 10 + c2 * 2];
            *(float2*)&Ls[row][c2 * 2] = v;
        }
        __syncthreads();
        const float* L = Ls[t];

        int a = 0;
        float best = -INFINITY, m = -INFINITY;
#pragma unroll
        for (int k = 0; k < 10; k++) {
            float g = bits_to_gumbel(tf_bits_part(keys.pw[0], keys.pw[1],
                                                  (uint32_t)(b * 80 + h * 10 + k)));
            float z = g + L[k];
            if (z > best) { best = z; a = k; }
            m = fmaxf(m, L[k]);
        }
        float s = 0.0f;
#pragma unroll
        for (int k = 0; k < 10; k++) s += __expf(L[k] - m);
        float lg = (L[a] - m) - __logf(s);
        int av = avail[b * 16 + 8 + h];
        out[(size_t)b * 16 + 8 + h] = (av > 0) ? (float)a : -1.0f;
        if (av > 0) lp += lg;
    }

    out[(size_t)BATCH * 16 + b] = lp;

    const size_t OFF = (size_t)BATCH * 17;
#pragma unroll
    for (int i = 0; i < 4; i++) {
        int4 v = *(const int4*)&avail[b * 16 + i * 4];
        *(float4*)&out[OFF + (size_t)b * 16 + i * 4] =
            make_float4((float)v.x, (float)v.y, (float)v.z, (float)v.w);
    }
}

// ---------------- host ----------------
extern "C" void kernel_launch(void* const* d_in, const int* in_sizes, int n_in,
                              void* d_out, int out_size)
{
    const float* x     = (const float*)d_in[0];
    const int*   avail = (const int*)  d_in[1];
    const float* Wsc   = (const float*)d_in[2];
    const float* bsc   = (const float*)d_in[3];
    const float* Wpow  = (const float*)d_in[4];
    const float* bpow  = (const float*)d_in[5];
    float* out = (float*)d_out;

    // JAX key(42) -> [0,42]; partitionable fold-like split + fold_in.
    SampKeys keys;
    for (int u = 0; u < 8; u++) {
        uint32_t o0, o1;
        threefry2x32(0u, 42u, 0u, (uint32_t)u, o0, o1);
        keys.sc[u][0] = o0; keys.sc[u][1] = o1;
    }
    threefry2x32(0u, 42u, 0u, 999u, keys.pw[0], keys.pw[1]);

    cudaFuncSetAttribute(gemm_kernel, cudaFuncAttributeMaxDynamicSharedMemorySize, G_SMEM);

    pack_kernel<<<(DIM * NCOLP + 255) / 256, 256>>>(Wsc, bsc, Wpow, bpow);
    packB_kernel<<<(26 * 16 * 32 + 255) / 256, 256>>>(Wsc, Wpow);
    gemm_kernel<<<NTILES, 256, G_SMEM>>>(x);
    sample_kernel<<<BATCH / 256, 256>>>(avail, out, keys);
}